// round 15
// baseline (speedup 1.0000x reference)
#include <cuda_runtime.h>
#include <cuda_fp16.h>
#include <cstdint>

#define T_LEN 4096
#define H_DIM 2048
#define G4    8192
#define NCTA  147
#define DPC   14
#define COLS  56
#define RTH   1024

static_assert(NCTA * DPC >= H_DIM, "coverage");

// ------------------------- device scratch (static) --------------------------
__device__ __align__(16) half  g_xhi [(size_t)T_LEN * H_DIM];
__device__ __align__(16) half  g_xlo [(size_t)T_LEN * H_DIM];
__device__ __align__(16) half  g_wihi[(size_t)G4 * H_DIM];   // Wi^T hi
__device__ __align__(16) half  g_wilo[(size_t)G4 * H_DIM];   // Wi^T lo
__device__ __align__(16) half  g_whT [(size_t)G4 * H_DIM];   // Wh^T
__device__ __align__(16) float g_xwi [(size_t)T_LEN * G4];   // x@Wi + b
__device__ __align__(16) half  g_hh  [2][H_DIM];             // fp16 h double buffer
__device__ __align__(16) unsigned g_cnt[32];                 // single arrival counter

// ------------------------- conversion kernels -------------------------------
__global__ void k_split_x(const float* __restrict__ x) {
    size_t i = (size_t)blockIdx.x * blockDim.x + threadIdx.x;
    if (i < (size_t)T_LEN * H_DIM) {
        float v = x[i];
        half h = __float2half_rn(v);
        g_xhi[i] = h;
        g_xlo[i] = __float2half_rn(v - __half2float(h));
    }
}

// z=0: Wi transpose + hi/lo split.  z=1: Wh transpose-convert + h0/counter init.
__global__ void k_tr_all(const float* __restrict__ wi, const float* __restrict__ wh,
                         const float* __restrict__ h0) {
    __shared__ float tile[32][33];
    const int n0 = blockIdx.x * 32, k0 = blockIdx.y * 32;
    const int tx = threadIdx.x, ty = threadIdx.y;
    const float* src = (blockIdx.z == 0) ? wi : wh;
#pragma unroll
    for (int r = 0; r < 32; r += 8)
        tile[ty + r][tx] = src[(size_t)(k0 + ty + r) * G4 + n0 + tx];
    __syncthreads();
    if (blockIdx.z == 0) {
#pragma unroll
        for (int r = 0; r < 32; r += 8) {
            const int n = n0 + ty + r, k = k0 + tx;
            float v = tile[tx][ty + r];
            half h = __float2half_rn(v);
            g_wihi[(size_t)n * H_DIM + k] = h;
            g_wilo[(size_t)n * H_DIM + k] = __float2half_rn(v - __half2float(h));
        }
    } else {
#pragma unroll
        for (int r = 0; r < 32; r += 8) {
            const int n = n0 + ty + r, k = k0 + tx;
            g_whT[(size_t)n * H_DIM + k] = __float2half_rn(tile[tx][ty + r]);
        }
        if (blockIdx.x == 0 && blockIdx.y == 0) {
            const int t = ty * 32 + tx;
            for (int i = t; i < H_DIM; i += 256)
                g_hh[1][i] = __float2half_rn(h0[i]);   // step 0 reads buffer 1
            if (t < 32) g_cnt[t] = 0u;
        }
    }
}

// --------------- fused 3-term fp16 TC GEMM: g_xwi = x @ Wi + b ---------------
#define BM 128
#define BN 128
#define BK 32
#define SSTR 56   // padded smem stride (halfs)

__device__ __forceinline__ void mma16816(float* d, const uint32_t* a, const uint32_t* b) {
    asm volatile(
        "mma.sync.aligned.m16n8k16.row.col.f32.f16.f16.f32 "
        "{%0,%1,%2,%3}, {%4,%5,%6,%7}, {%8,%9}, {%0,%1,%2,%3};\n"
        : "+f"(d[0]), "+f"(d[1]), "+f"(d[2]), "+f"(d[3])
        : "r"(a[0]), "r"(a[1]), "r"(a[2]), "r"(a[3]), "r"(b[0]), "r"(b[1]));
}

__global__ void __launch_bounds__(256) k_gemm(const float* __restrict__ bias) {
    extern __shared__ __align__(16) half smem_g[];
    half* sAh = smem_g;
    half* sAl = sAh + BM * SSTR;
    half* sBh = sAl + BM * SSTR;
    half* sBl = sBh + BN * SSTR;

    const int tid = threadIdx.x;
    const int lane = tid & 31, wid = tid >> 5;
    const int wm = wid & 1, wn = wid >> 1;                  // warp tile 64(M) x 32(N)
    const int bm = blockIdx.y * BM, bn = blockIdx.x * BN;

    const int lrow = tid >> 2;                              // 0..63
    const int lpart = (tid & 3) * 8;                        // halfs
    const size_t rstep = (size_t)64 * H_DIM;
    const half* gAh = g_xhi  + (size_t)(bm + lrow) * H_DIM + lpart;
    const half* gAl = g_xlo  + (size_t)(bm + lrow) * H_DIM + lpart;
    const half* gBh = g_wihi + (size_t)(bn + lrow) * H_DIM + lpart;
    const half* gBl = g_wilo + (size_t)(bn + lrow) * H_DIM + lpart;

    half* pA0 = &sAh[lrow * SSTR + lpart]; half* pA1 = pA0 + 64 * SSTR;
    half* pL0 = &sAl[lrow * SSTR + lpart]; half* pL1 = pL0 + 64 * SSTR;
    half* pB0 = &sBh[lrow * SSTR + lpart]; half* pB1 = pB0 + 64 * SSTR;
    half* pC0 = &sBl[lrow * SSTR + lpart]; half* pC1 = pC0 + 64 * SSTR;

    float d[4][4][4];
#pragma unroll
    for (int i = 0; i < 4; i++)
#pragma unroll
        for (int j = 0; j < 4; j++)
#pragma unroll
            for (int v = 0; v < 4; v++) d[i][j][v] = 0.f;

    uint4 vah0 = *(const uint4*)(gAh);           uint4 vah1 = *(const uint4*)(gAh + rstep);
    uint4 val0 = *(const uint4*)(gAl);           uint4 val1 = *(const uint4*)(gAl + rstep);
    uint4 vbh0 = *(const uint4*)(gBh);           uint4 vbh1 = *(const uint4*)(gBh + rstep);
    uint4 vbl0 = *(const uint4*)(gBl);           uint4 vbl1 = *(const uint4*)(gBl + rstep);

    for (int k0 = 0; k0 < H_DIM; k0 += BK) {
        __syncthreads();
        *(uint4*)pA0 = vah0; *(uint4*)pA1 = vah1;
        *(uint4*)pL0 = val0; *(uint4*)pL1 = val1;
        *(uint4*)pB0 = vbh0; *(uint4*)pB1 = vbh1;
        *(uint4*)pC0 = vbl0; *(uint4*)pC1 = vbl1;
        __syncthreads();
        if (k0 + BK < H_DIM) {
            vah0 = *(const uint4*)(gAh + k0 + BK); vah1 = *(const uint4*)(gAh + k0 + BK + rstep);
            val0 = *(const uint4*)(gAl + k0 + BK); val1 = *(const uint4*)(gAl + k0 + BK + rstep);
            vbh0 = *(const uint4*)(gBh + k0 + BK); vbh1 = *(const uint4*)(gBh + k0 + BK + rstep);
            vbl0 = *(const uint4*)(gBl + k0 + BK); vbl1 = *(const uint4*)(gBl + k0 + BK + rstep);
        }
#pragma unroll
        for (int kk = 0; kk < 2; kk++) {
            const int kh = kk * 16;
            const int ar = lane >> 2, ak = 2 * (lane & 3);
            uint32_t afh[4][4], afl[4][4], bfh[4][2], bfl[4][2];
#pragma unroll
            for (int i = 0; i < 4; i++) {
                const int ro = (wm * 64 + i * 16 + ar) * SSTR + kh + ak;
                const half* ph = &sAh[ro];
                afh[i][0] = *(const uint32_t*)ph;
                afh[i][1] = *(const uint32_t*)(ph + 8 * SSTR);
                afh[i][2] = *(const uint32_t*)(ph + 8);
                afh[i][3] = *(const uint32_t*)(ph + 8 * SSTR + 8);
                const half* pl = &sAl[ro];
                afl[i][0] = *(const uint32_t*)pl;
                afl[i][1] = *(const uint32_t*)(pl + 8 * SSTR);
                afl[i][2] = *(const uint32_t*)(pl + 8);
                afl[i][3] = *(const uint32_t*)(pl + 8 * SSTR + 8);
            }
#pragma unroll
            for (int j = 0; j < 4; j++) {
                const int ro = (wn * 32 + j * 8 + ar) * SSTR + kh + ak;
                const half* ph = &sBh[ro];
                bfh[j][0] = *(const uint32_t*)ph;
                bfh[j][1] = *(const uint32_t*)(ph + 8);
                const half* pl = &sBl[ro];
                bfl[j][0] = *(const uint32_t*)pl;
                bfl[j][1] = *(const uint32_t*)(pl + 8);
            }
#pragma unroll
            for (int i = 0; i < 4; i++)
#pragma unroll
                for (int j = 0; j < 4; j++) {
                    mma16816(d[i][j], afh[i], bfh[j]);   // xhi @ whi
                    mma16816(d[i][j], afh[i], bfl[j]);   // xhi @ wlo
                    mma16816(d[i][j], afl[i], bfh[j]);   // xlo @ whi
                }
        }
    }

#pragma unroll
    for (int i = 0; i < 4; i++) {
        int r = bm + wm * 64 + i * 16 + (lane >> 2);
#pragma unroll
        for (int j = 0; j < 4; j++) {
            int c = bn + wn * 32 + j * 8 + 2 * (lane & 3);
            float b0 = bias[c], b1 = bias[c + 1];
            float* o0 = &g_xwi[(size_t)r * G4 + c];
            float* o1 = o0 + (size_t)8 * G4;
            o0[0] = d[i][j][0] + b0;
            o0[1] = d[i][j][1] + b1;
            o1[0] = d[i][j][2] + b0;
            o1[1] = d[i][j][3] + b1;
        }
    }
}

// ------------------------- persistent LSTM recurrence -----------------------
__device__ __forceinline__ float sigf(float x) { return 1.f / (1.f + __expf(-x)); }
__device__ __forceinline__ float tanhfast(float x) { return 1.f - 2.f / (__expf(2.f * x) + 1.f); }

// 32 warps: warp w -> column group (w>>2) of 7 cols, k-quarter (w&3) of 512.
// out layout: [ c_f (H) | h_f (H) | ys (T*H) ]
__global__ void __launch_bounds__(RTH, 1) k_lstm(
    const float* __restrict__ c0, float* __restrict__ out)
{
    extern __shared__ __align__(16) half sW[];   // [COLS][H_DIM]
    __shared__ float ybuf[4 * COLS];

    const int tid = threadIdx.x;
    const int wid = tid >> 5, lane = tid & 31;
    const int cg = wid >> 2;          // 0..7: column group (7 cols)
    const int kq = wid & 3;           // k quarter: 0..3 (512 elems)
    const int d0 = blockIdx.x * DPC;
    float* ys = out + 2 * H_DIM;

    // load this CTA's 56 weight columns into smem (coalesced, once per run)
    const int NV = COLS * (H_DIM / 8);
    for (int i = tid; i < NV; i += RTH) {
        int c = i >> 8;                 // / (H_DIM/8)
        int k8 = (i & 255) * 8;
        int gate = c / DPC, di = c - gate * DPC;
        int dgc = d0 + di;
        uint4 v = make_uint4(0u, 0u, 0u, 0u);
        if (dgc < H_DIM)
            v = *(const uint4*)&g_whT[((size_t)(gate * H_DIM + dgc)) * H_DIM + k8];
        *(uint4*)&sW[(size_t)c * H_DIM + k8] = v;
    }

    const int dg = d0 + tid;
    const bool gt = (tid < DPC) && (dg < H_DIM);

    float c_state = gt ? c0[dg] : 0.f;
    float h_last = 0.f;

    // prefetch x@Wi+b gate contributions for step 0
    float xw0 = 0.f, xw1 = 0.f, xw2 = 0.f, xw3 = 0.f;
    if (gt) {
        const float* xp = g_xwi + dg;
        xw0 = xp[0];
        xw1 = xp[H_DIM];
        xw2 = xp[2 * H_DIM];
        xw3 = xp[3 * H_DIM];
    }
    __syncthreads();

    // this warp's lane covers halfs [kq*512 + lane*16, +16)
    const int koff = kq * 512 + lane * 16;

    for (int t = 0; t < T_LEN; t++) {
        // fp16 h of previous step (double-buffered; L2-coherent loads)
        const uint4* hsrc = (const uint4*)&g_hh[(t & 1) ^ 1][koff];
        uint4 hv0 = __ldcg(hsrc);
        uint4 hv1 = __ldcg(hsrc + 1);

        const half2 ha0 = *reinterpret_cast<const half2*>(&hv0.x);
        const half2 ha1 = *reinterpret_cast<const half2*>(&hv0.y);
        const half2 ha2 = *reinterpret_cast<const half2*>(&hv0.z);
        const half2 ha3 = *reinterpret_cast<const half2*>(&hv0.w);
        const half2 hb0 = *reinterpret_cast<const half2*>(&hv1.x);
        const half2 hb1 = *reinterpret_cast<const half2*>(&hv1.y);
        const half2 hb2 = *reinterpret_cast<const half2*>(&hv1.z);
        const half2 hb3 = *reinterpret_cast<const half2*>(&hv1.w);

        const half* wp0 = &sW[(size_t)(cg * 7) * H_DIM + koff];

#pragma unroll
        for (int j = 0; j < 7; j++) {
            const half* wp = wp0 + (size_t)j * H_DIM;
            uint4 w0 = *(const uint4*)(wp);
            uint4 w1 = *(const uint4*)(wp + 8);
            // two independent 4-deep chains (8 products each)
            half2 a = __hmul2(*reinterpret_cast<half2*>(&w0.x), ha0);
            a = __hfma2(*reinterpret_cast<half2*>(&w0.y), ha1, a);
            a = __hfma2(*reinterpret_cast<half2*>(&w0.z), ha2, a);
            a = __hfma2(*reinterpret_cast<half2*>(&w0.w), ha3, a);
            half2 bch = __hmul2(*reinterpret_cast<half2*>(&w1.x), hb0);
            bch = __hfma2(*reinterpret_cast<half2*>(&w1.y), hb1, bch);
            bch = __hfma2(*reinterpret_cast<half2*>(&w1.z), hb2, bch);
            bch = __hfma2(*reinterpret_cast<half2*>(&w1.w), hb3, bch);

            float2 fa = __half22float2(a);
            float2 fb = __half22float2(bch);
            float v = (fa.x + fa.y) + (fb.x + fb.y);

            v += __shfl_xor_sync(0xffffffffu, v, 16);
            v += __shfl_xor_sync(0xffffffffu, v, 8);
            v += __shfl_xor_sync(0xffffffffu, v, 4);
            v += __shfl_xor_sync(0xffffffffu, v, 2);
            v += __shfl_xor_sync(0xffffffffu, v, 1);
            if (lane == 0) ybuf[kq * COLS + cg * 7 + j] = v;
        }
        __syncthreads();                                   // (A) ybuf ready

        if (gt) {
            float yi = ybuf[tid]
                     + ybuf[COLS + tid]
                     + ybuf[2 * COLS + tid]
                     + ybuf[3 * COLS + tid] + xw0;
            float yf = ybuf[DPC + tid]
                     + ybuf[COLS + DPC + tid]
                     + ybuf[2 * COLS + DPC + tid]
                     + ybuf[3 * COLS + DPC + tid] + xw1;
            float yg = ybuf[2 * DPC + tid]
                     + ybuf[COLS + 2 * DPC + tid]
                     + ybuf[2 * COLS + 2 * DPC + tid]
                     + ybuf[3 * COLS + 2 * DPC + tid] + xw2;
            float yo = ybuf[3 * DPC + tid]
                     + ybuf[COLS + 3 * DPC + tid]
                     + ybuf[2 * COLS + 3 * DPC + tid]
                     + ybuf[3 * COLS + 3 * DPC + tid] + xw3;
            float ig = sigf(yi);
            float fg = sigf(yf);
            float gg = tanhfast(yg);
            float og = sigf(yo);
            c_state = fg * c_state + ig * gg;
            h_last = og * tanhfast(c_state);
            g_hh[t & 1][dg] = __float2half_rn(h_last);     // broadcast first
            ys[(size_t)t * H_DIM + dg] = h_last;
        }
        __syncthreads();   // (B) all h stores happen-before the arriving thread

        // arrive: one non-gate thread (proven R8 pattern, best measured barrier)
        if (tid == RTH - 1) {
            __threadfence();                               // release
            atomicAdd(&g_cnt[0], 1u);
        }
        // gate threads prefetch next xw while tid 1023 polls (hides DRAM latency)
        if (gt && t + 1 < T_LEN) {
            const float* xp = g_xwi + (size_t)(t + 1) * G4 + dg;
            xw0 = xp[0];
            xw1 = xp[H_DIM];
            xw2 = xp[2 * H_DIM];
            xw3 = xp[3 * H_DIM];
        }
        if (tid == RTH - 1) {
            const unsigned tgt = (unsigned)(t + 1) * (unsigned)NCTA;
            volatile unsigned* pb = &g_cnt[0];
            while (*pb < tgt) __nanosleep(32);
            __threadfence();                               // acquire
        }
        __syncthreads();                                   // (C) release all
    }

    if (gt) {
        out[dg] = c_state;           // c_f
        out[H_DIM + dg] = h_last;    // h_f
    }
}

// ------------------------- launch -------------------------------------------
extern "C" void kernel_launch(void* const* d_in, const int* in_sizes, int n_in,
                              void* d_out, int out_size) {
    const float* x  = (const float*)d_in[0];
    const float* c0 = (const float*)d_in[1];
    const float* h0 = (const float*)d_in[2];
    const float* Wi = (const float*)d_in[3];
    const float* Wh = (const float*)d_in[4];
    const float* b  = (const float*)d_in[5];
    float* out = (float*)d_out;

    (void)in_sizes; (void)n_in; (void)out_size;

    static int attr_set = 0;
    const int gemm_smem = 4 * BM * SSTR * (int)sizeof(half);        // 57344
    const int lstm_smem = COLS * H_DIM * (int)sizeof(half);         // 229376
    if (!attr_set) {
        cudaFuncSetAttribute(k_gemm, cudaFuncAttributeMaxDynamicSharedMemorySize, gemm_smem);
        cudaFuncSetAttribute(k_lstm, cudaFuncAttributeMaxDynamicSharedMemorySize, lstm_smem);
        attr_set = 1;
    }

    // launch order keeps k_lstm as the 4th launch -> ncu (-s5 -c1) profiles it
    k_split_x<<<(T_LEN * H_DIM + 255) / 256, 256>>>(x);
    k_tr_all<<<dim3(G4 / 32, H_DIM / 32, 2), dim3(32, 8)>>>(Wi, Wh, h0);

    dim3 gg(G4 / BN, T_LEN / BM);
    k_gemm<<<gg, 256, gemm_smem>>>(b);

    k_lstm<<<NCTA, RTH, lstm_smem>>>(c0, out);
}

// round 16
// speedup vs baseline: 1.4820x; 1.4820x over previous
#include <cuda_runtime.h>
#include <cuda_fp16.h>
#include <cstdint>

#define T_LEN 4096
#define H_DIM 2048
#define G4    8192
#define NCTA  147
#define DPC   14
#define COLS  56
#define RTH   512

static_assert(NCTA * DPC >= H_DIM, "coverage");

// ------------------------- device scratch (static) --------------------------
__device__ __align__(16) half  g_xhi [(size_t)T_LEN * H_DIM];
__device__ __align__(16) half  g_xlo [(size_t)T_LEN * H_DIM];
__device__ __align__(16) half  g_wihi[(size_t)G4 * H_DIM];   // Wi^T hi
__device__ __align__(16) half  g_wilo[(size_t)G4 * H_DIM];   // Wi^T lo
__device__ __align__(16) half  g_whT [(size_t)G4 * H_DIM];   // Wh^T
__device__ __align__(16) float g_xwi [(size_t)T_LEN * G4];   // x@Wi + b
__device__ __align__(16) half  g_hh  [2][H_DIM];             // fp16 h double buffer
__device__ __align__(16) unsigned g_cnt[32];                 // single arrival counter

// ------------------------- conversion kernels -------------------------------
__global__ void k_split_x(const float* __restrict__ x) {
    size_t i = (size_t)blockIdx.x * blockDim.x + threadIdx.x;
    if (i < (size_t)T_LEN * H_DIM) {
        float v = x[i];
        half h = __float2half_rn(v);
        g_xhi[i] = h;
        g_xlo[i] = __float2half_rn(v - __half2float(h));
    }
}

// z=0: Wi transpose + hi/lo split.  z=1: Wh transpose-convert + h0/counter init.
__global__ void k_tr_all(const float* __restrict__ wi, const float* __restrict__ wh,
                         const float* __restrict__ h0) {
    __shared__ float tile[32][33];
    const int n0 = blockIdx.x * 32, k0 = blockIdx.y * 32;
    const int tx = threadIdx.x, ty = threadIdx.y;
    const float* src = (blockIdx.z == 0) ? wi : wh;
#pragma unroll
    for (int r = 0; r < 32; r += 8)
        tile[ty + r][tx] = src[(size_t)(k0 + ty + r) * G4 + n0 + tx];
    __syncthreads();
    if (blockIdx.z == 0) {
#pragma unroll
        for (int r = 0; r < 32; r += 8) {
            const int n = n0 + ty + r, k = k0 + tx;
            float v = tile[tx][ty + r];
            half h = __float2half_rn(v);
            g_wihi[(size_t)n * H_DIM + k] = h;
            g_wilo[(size_t)n * H_DIM + k] = __float2half_rn(v - __half2float(h));
        }
    } else {
#pragma unroll
        for (int r = 0; r < 32; r += 8) {
            const int n = n0 + ty + r, k = k0 + tx;
            g_whT[(size_t)n * H_DIM + k] = __float2half_rn(tile[tx][ty + r]);
        }
        if (blockIdx.x == 0 && blockIdx.y == 0) {
            const int t = ty * 32 + tx;
            for (int i = t; i < H_DIM; i += 256)
                g_hh[1][i] = __float2half_rn(h0[i]);   // step 0 reads buffer 1
            if (t < 32) g_cnt[t] = 0u;
        }
    }
}

// --------------- fused 3-term fp16 TC GEMM: g_xwi = x @ Wi + b ---------------
#define BM 128
#define BN 128
#define BK 32
#define SSTR 56   // padded smem stride (halfs)

__device__ __forceinline__ void mma16816(float* d, const uint32_t* a, const uint32_t* b) {
    asm volatile(
        "mma.sync.aligned.m16n8k16.row.col.f32.f16.f16.f32 "
        "{%0,%1,%2,%3}, {%4,%5,%6,%7}, {%8,%9}, {%0,%1,%2,%3};\n"
        : "+f"(d[0]), "+f"(d[1]), "+f"(d[2]), "+f"(d[3])
        : "r"(a[0]), "r"(a[1]), "r"(a[2]), "r"(a[3]), "r"(b[0]), "r"(b[1]));
}

__global__ void __launch_bounds__(256) k_gemm(const float* __restrict__ bias) {
    extern __shared__ __align__(16) half smem_g[];
    half* sAh = smem_g;
    half* sAl = sAh + BM * SSTR;
    half* sBh = sAl + BM * SSTR;
    half* sBl = sBh + BN * SSTR;

    const int tid = threadIdx.x;
    const int lane = tid & 31, wid = tid >> 5;
    const int wm = wid & 1, wn = wid >> 1;                  // warp tile 64(M) x 32(N)
    const int bm = blockIdx.y * BM, bn = blockIdx.x * BN;

    const int lrow = tid >> 2;                              // 0..63
    const int lpart = (tid & 3) * 8;                        // halfs
    const size_t rstep = (size_t)64 * H_DIM;
    const half* gAh = g_xhi  + (size_t)(bm + lrow) * H_DIM + lpart;
    const half* gAl = g_xlo  + (size_t)(bm + lrow) * H_DIM + lpart;
    const half* gBh = g_wihi + (size_t)(bn + lrow) * H_DIM + lpart;
    const half* gBl = g_wilo + (size_t)(bn + lrow) * H_DIM + lpart;

    half* pA0 = &sAh[lrow * SSTR + lpart]; half* pA1 = pA0 + 64 * SSTR;
    half* pL0 = &sAl[lrow * SSTR + lpart]; half* pL1 = pL0 + 64 * SSTR;
    half* pB0 = &sBh[lrow * SSTR + lpart]; half* pB1 = pB0 + 64 * SSTR;
    half* pC0 = &sBl[lrow * SSTR + lpart]; half* pC1 = pC0 + 64 * SSTR;

    float d[4][4][4];
#pragma unroll
    for (int i = 0; i < 4; i++)
#pragma unroll
        for (int j = 0; j < 4; j++)
#pragma unroll
            for (int v = 0; v < 4; v++) d[i][j][v] = 0.f;

    uint4 vah0 = *(const uint4*)(gAh);           uint4 vah1 = *(const uint4*)(gAh + rstep);
    uint4 val0 = *(const uint4*)(gAl);           uint4 val1 = *(const uint4*)(gAl + rstep);
    uint4 vbh0 = *(const uint4*)(gBh);           uint4 vbh1 = *(const uint4*)(gBh + rstep);
    uint4 vbl0 = *(const uint4*)(gBl);           uint4 vbl1 = *(const uint4*)(gBl + rstep);

    for (int k0 = 0; k0 < H_DIM; k0 += BK) {
        __syncthreads();
        *(uint4*)pA0 = vah0; *(uint4*)pA1 = vah1;
        *(uint4*)pL0 = val0; *(uint4*)pL1 = val1;
        *(uint4*)pB0 = vbh0; *(uint4*)pB1 = vbh1;
        *(uint4*)pC0 = vbl0; *(uint4*)pC1 = vbl1;
        __syncthreads();
        if (k0 + BK < H_DIM) {
            vah0 = *(const uint4*)(gAh + k0 + BK); vah1 = *(const uint4*)(gAh + k0 + BK + rstep);
            val0 = *(const uint4*)(gAl + k0 + BK); val1 = *(const uint4*)(gAl + k0 + BK + rstep);
            vbh0 = *(const uint4*)(gBh + k0 + BK); vbh1 = *(const uint4*)(gBh + k0 + BK + rstep);
            vbl0 = *(const uint4*)(gBl + k0 + BK); vbl1 = *(const uint4*)(gBl + k0 + BK + rstep);
        }
#pragma unroll
        for (int kk = 0; kk < 2; kk++) {
            const int kh = kk * 16;
            const int ar = lane >> 2, ak = 2 * (lane & 3);
            uint32_t afh[4][4], afl[4][4], bfh[4][2], bfl[4][2];
#pragma unroll
            for (int i = 0; i < 4; i++) {
                const int ro = (wm * 64 + i * 16 + ar) * SSTR + kh + ak;
                const half* ph = &sAh[ro];
                afh[i][0] = *(const uint32_t*)ph;
                afh[i][1] = *(const uint32_t*)(ph + 8 * SSTR);
                afh[i][2] = *(const uint32_t*)(ph + 8);
                afh[i][3] = *(const uint32_t*)(ph + 8 * SSTR + 8);
                const half* pl = &sAl[ro];
                afl[i][0] = *(const uint32_t*)pl;
                afl[i][1] = *(const uint32_t*)(pl + 8 * SSTR);
                afl[i][2] = *(const uint32_t*)(pl + 8);
                afl[i][3] = *(const uint32_t*)(pl + 8 * SSTR + 8);
            }
#pragma unroll
            for (int j = 0; j < 4; j++) {
                const int ro = (wn * 32 + j * 8 + ar) * SSTR + kh + ak;
                const half* ph = &sBh[ro];
                bfh[j][0] = *(const uint32_t*)ph;
                bfh[j][1] = *(const uint32_t*)(ph + 8);
                const half* pl = &sBl[ro];
                bfl[j][0] = *(const uint32_t*)pl;
                bfl[j][1] = *(const uint32_t*)(pl + 8);
            }
#pragma unroll
            for (int i = 0; i < 4; i++)
#pragma unroll
                for (int j = 0; j < 4; j++) {
                    mma16816(d[i][j], afh[i], bfh[j]);   // xhi @ whi
                    mma16816(d[i][j], afh[i], bfl[j]);   // xhi @ wlo
                    mma16816(d[i][j], afl[i], bfh[j]);   // xlo @ whi
                }
        }
    }

#pragma unroll
    for (int i = 0; i < 4; i++) {
        int r = bm + wm * 64 + i * 16 + (lane >> 2);
#pragma unroll
        for (int j = 0; j < 4; j++) {
            int c = bn + wn * 32 + j * 8 + 2 * (lane & 3);
            float b0 = bias[c], b1 = bias[c + 1];
            float* o0 = &g_xwi[(size_t)r * G4 + c];
            float* o1 = o0 + (size_t)8 * G4;
            o0[0] = d[i][j][0] + b0;
            o0[1] = d[i][j][1] + b1;
            o1[0] = d[i][j][2] + b0;
            o1[1] = d[i][j][3] + b1;
        }
    }
}

// ------------------------- persistent LSTM recurrence -----------------------
__device__ __forceinline__ float sigf(float x) { return 1.f / (1.f + __expf(-x)); }
__device__ __forceinline__ float tanhfast(float x) { return 1.f - 2.f / (__expf(2.f * x) + 1.f); }

// 16 warps: warp w -> column group (w>>1) of 7 cols, k-half (w&1) of 1024.
// R8-measured-best math (fp32 accumulators); R13-measured-best barrier.
// out layout: [ c_f (H) | h_f (H) | ys (T*H) ]
__global__ void __launch_bounds__(RTH, 1) k_lstm(
    const float* __restrict__ c0, float* __restrict__ out)
{
    extern __shared__ __align__(16) half sW[];   // [COLS][H_DIM]
    __shared__ float ybuf[2 * COLS];

    const int tid = threadIdx.x;
    const int wid = tid >> 5, lane = tid & 31;
    const int cg = wid >> 1;          // 0..7: column group (7 cols)
    const int kh = wid & 1;           // k half: 0 or 1
    const int d0 = blockIdx.x * DPC;
    float* ys = out + 2 * H_DIM;

    // load this CTA's 56 weight columns into smem (coalesced, once per run)
    const int NV = COLS * (H_DIM / 8);
    for (int i = tid; i < NV; i += RTH) {
        int c = i >> 8;                 // / (H_DIM/8)
        int k8 = (i & 255) * 8;
        int gate = c / DPC, di = c - gate * DPC;
        int dgc = d0 + di;
        uint4 v = make_uint4(0u, 0u, 0u, 0u);
        if (dgc < H_DIM)
            v = *(const uint4*)&g_whT[((size_t)(gate * H_DIM + dgc)) * H_DIM + k8];
        *(uint4*)&sW[(size_t)c * H_DIM + k8] = v;
    }

    const int dg = d0 + tid;
    const bool gt = (tid < DPC) && (dg < H_DIM);

    float c_state = gt ? c0[dg] : 0.f;
    float h_last = 0.f;

    // prefetch x@Wi+b gate contributions for step 0
    float xw0 = 0.f, xw1 = 0.f, xw2 = 0.f, xw3 = 0.f;
    if (gt) {
        const float* xp = g_xwi + dg;
        xw0 = xp[0];
        xw1 = xp[H_DIM];
        xw2 = xp[2 * H_DIM];
        xw3 = xp[3 * H_DIM];
    }
    __syncthreads();

    for (int t = 0; t < T_LEN; t++) {
        // fp16 h of previous step (double-buffered; L2-coherent loads), this k-half
        const uint4* hsrc = (const uint4*)&g_hh[(t & 1) ^ 1][kh * 1024];
        uint4 hv[4];
#pragma unroll
        for (int m = 0; m < 4; m++) hv[m] = __ldcg(hsrc + m * 32 + lane);

        float acc[7];
#pragma unroll
        for (int j = 0; j < 7; j++) acc[j] = 0.f;

#pragma unroll
        for (int m = 0; m < 4; m++) {
            const int kb = kh * 1024 + (m * 32 + lane) * 8;
            const half2 h0 = *reinterpret_cast<const half2*>(&hv[m].x);
            const half2 h1 = *reinterpret_cast<const half2*>(&hv[m].y);
            const half2 h2 = *reinterpret_cast<const half2*>(&hv[m].z);
            const half2 h3 = *reinterpret_cast<const half2*>(&hv[m].w);
#pragma unroll
            for (int j = 0; j < 7; j++) {
                uint4 wv = *(const uint4*)&sW[(size_t)(cg * 7 + j) * H_DIM + kb];
                half2 p = __hmul2(*reinterpret_cast<half2*>(&wv.x), h0);
                p = __hfma2(*reinterpret_cast<half2*>(&wv.y), h1, p);
                p = __hfma2(*reinterpret_cast<half2*>(&wv.z), h2, p);
                p = __hfma2(*reinterpret_cast<half2*>(&wv.w), h3, p);
                float2 pf = __half22float2(p);
                acc[j] += pf.x + pf.y;
            }
        }

#pragma unroll
        for (int j = 0; j < 7; j++) {
            float v = acc[j];
            v += __shfl_xor_sync(0xffffffffu, v, 16);
            v += __shfl_xor_sync(0xffffffffu, v, 8);
            v += __shfl_xor_sync(0xffffffffu, v, 4);
            v += __shfl_xor_sync(0xffffffffu, v, 2);
            v += __shfl_xor_sync(0xffffffffu, v, 1);
            if (lane == 0) ybuf[kh * COLS + cg * 7 + j] = v;
        }
        __syncthreads();                                   // (A) ybuf ready

        if (gt) {
            float yi = ybuf[tid]           + ybuf[COLS + tid]           + xw0;
            float yf = ybuf[DPC + tid]     + ybuf[COLS + DPC + tid]     + xw1;
            float yg = ybuf[2 * DPC + tid] + ybuf[COLS + 2 * DPC + tid] + xw2;
            float yo = ybuf[3 * DPC + tid] + ybuf[COLS + 3 * DPC + tid] + xw3;
            float ig = sigf(yi);
            float fg = sigf(yf);
            float gg = tanhfast(yg);
            float og = sigf(yo);
            c_state = fg * c_state + ig * gg;
            h_last = og * tanhfast(c_state);
            g_hh[t & 1][dg] = __float2half_rn(h_last);     // broadcast first
            ys[(size_t)t * H_DIM + dg] = h_last;
            // arrival directly on the gate warp: fence covers all gt lanes'
            // stores (same warp, program order), then lane 0 arrives.
            __threadfence();                               // release
            if (tid == 0) atomicAdd(&g_cnt[0], 1u);        // REDG, no return
            // prefetch next xw during the global wait (hides DRAM latency)
            if (t + 1 < T_LEN) {
                const float* xp = g_xwi + (size_t)(t + 1) * G4 + dg;
                xw0 = xp[0];
                xw1 = xp[H_DIM];
                xw2 = xp[2 * H_DIM];
                xw3 = xp[3 * H_DIM];
            }
        }
        // single poller, single volatile word, tight spin (R13-measured best)
        if (tid == RTH - 1) {
            volatile unsigned* pc = &g_cnt[0];
            const unsigned tgt = (unsigned)(t + 1) * (unsigned)NCTA;
            while (*pc < tgt) { }
            __threadfence();                               // acquire
        }
        __syncthreads();                                   // (B) release all
    }

    if (gt) {
        out[dg] = c_state;           // c_f
        out[H_DIM + dg] = h_last;    // h_f
    }
}

// ------------------------- launch -------------------------------------------
extern "C" void kernel_launch(void* const* d_in, const int* in_sizes, int n_in,
                              void* d_out, int out_size) {
    const float* x  = (const float*)d_in[0];
    const float* c0 = (const float*)d_in[1];
    const float* h0 = (const float*)d_in[2];
    const float* Wi = (const float*)d_in[3];
    const float* Wh = (const float*)d_in[4];
    const float* b  = (const float*)d_in[5];
    float* out = (float*)d_out;

    (void)in_sizes; (void)n_in; (void)out_size;

    static int attr_set = 0;
    const int gemm_smem = 4 * BM * SSTR * (int)sizeof(half);        // 57344
    const int lstm_smem = COLS * H_DIM * (int)sizeof(half);         // 229376
    if (!attr_set) {
        cudaFuncSetAttribute(k_gemm, cudaFuncAttributeMaxDynamicSharedMemorySize, gemm_smem);
        cudaFuncSetAttribute(k_lstm, cudaFuncAttributeMaxDynamicSharedMemorySize, lstm_smem);
        attr_set = 1;
    }

    // launch order keeps k_lstm as the 4th launch -> ncu (-s5 -c1) profiles it
    k_split_x<<<(T_LEN * H_DIM + 255) / 256, 256>>>(x);
    k_tr_all<<<dim3(G4 / 32, H_DIM / 32, 2), dim3(32, 8)>>>(Wi, Wh, h0);

    dim3 gg(G4 / BN, T_LEN / BM);
    k_gemm<<<gg, 256, gemm_smem>>>(b);

    k_lstm<<<NCTA, RTH, lstm_smem>>>(c0, out);
}

// round 17
// speedup vs baseline: 1.5176x; 1.0240x over previous
#include <cuda_runtime.h>
#include <cuda_fp16.h>
#include <cstdint>

#define T_LEN 4096
#define H_DIM 2048
#define G4    8192
#define NCTA  147
#define DPC   14
#define COLS  56
#define RTH   512

static_assert(NCTA * DPC >= H_DIM, "coverage");

// ------------------------- device scratch (static) --------------------------
__device__ __align__(16) half  g_xhi [(size_t)T_LEN * H_DIM];
__device__ __align__(16) half  g_xlo [(size_t)T_LEN * H_DIM];
__device__ __align__(16) half  g_wihi[(size_t)G4 * H_DIM];   // Wi^T hi
__device__ __align__(16) half  g_wilo[(size_t)G4 * H_DIM];   // Wi^T lo
__device__ __align__(16) half  g_whT [(size_t)G4 * H_DIM];   // Wh^T
__device__ __align__(16) float g_xwi [(size_t)T_LEN * G4];   // x@Wi + b
__device__ __align__(16) half  g_hh  [2][H_DIM];             // fp16 h double buffer
__device__ __align__(16) unsigned g_cnt[32];                 // single arrival counter

// ------------------------- conversion kernels -------------------------------
__global__ void k_split_x(const float* __restrict__ x) {
    size_t i = (size_t)blockIdx.x * blockDim.x + threadIdx.x;
    if (i < (size_t)T_LEN * H_DIM) {
        float v = x[i];
        half h = __float2half_rn(v);
        g_xhi[i] = h;
        g_xlo[i] = __float2half_rn(v - __half2float(h));
    }
}

// z=0: Wi transpose + hi/lo split.  z=1: Wh transpose-convert + h0/counter init.
__global__ void k_tr_all(const float* __restrict__ wi, const float* __restrict__ wh,
                         const float* __restrict__ h0) {
    __shared__ float tile[32][33];
    const int n0 = blockIdx.x * 32, k0 = blockIdx.y * 32;
    const int tx = threadIdx.x, ty = threadIdx.y;
    const float* src = (blockIdx.z == 0) ? wi : wh;
#pragma unroll
    for (int r = 0; r < 32; r += 8)
        tile[ty + r][tx] = src[(size_t)(k0 + ty + r) * G4 + n0 + tx];
    __syncthreads();
    if (blockIdx.z == 0) {
#pragma unroll
        for (int r = 0; r < 32; r += 8) {
            const int n = n0 + ty + r, k = k0 + tx;
            float v = tile[tx][ty + r];
            half h = __float2half_rn(v);
            g_wihi[(size_t)n * H_DIM + k] = h;
            g_wilo[(size_t)n * H_DIM + k] = __float2half_rn(v - __half2float(h));
        }
    } else {
#pragma unroll
        for (int r = 0; r < 32; r += 8) {
            const int n = n0 + ty + r, k = k0 + tx;
            g_whT[(size_t)n * H_DIM + k] = __float2half_rn(tile[tx][ty + r]);
        }
        if (blockIdx.x == 0 && blockIdx.y == 0) {
            const int t = ty * 32 + tx;
            for (int i = t; i < H_DIM; i += 256)
                g_hh[1][i] = __float2half_rn(h0[i]);   // step 0 reads buffer 1
            if (t < 32) g_cnt[t] = 0u;
        }
    }
}

// --------------- fused 3-term fp16 TC GEMM: g_xwi = x @ Wi + b ---------------
#define BM 128
#define BN 128
#define BK 32
#define SSTR 56   // padded smem stride (halfs)

__device__ __forceinline__ void mma16816(float* d, const uint32_t* a, const uint32_t* b) {
    asm volatile(
        "mma.sync.aligned.m16n8k16.row.col.f32.f16.f16.f32 "
        "{%0,%1,%2,%3}, {%4,%5,%6,%7}, {%8,%9}, {%0,%1,%2,%3};\n"
        : "+f"(d[0]), "+f"(d[1]), "+f"(d[2]), "+f"(d[3])
        : "r"(a[0]), "r"(a[1]), "r"(a[2]), "r"(a[3]), "r"(b[0]), "r"(b[1]));
}

__global__ void __launch_bounds__(256) k_gemm(const float* __restrict__ bias) {
    extern __shared__ __align__(16) half smem_g[];
    half* sAh = smem_g;
    half* sAl = sAh + BM * SSTR;
    half* sBh = sAl + BM * SSTR;
    half* sBl = sBh + BN * SSTR;

    const int tid = threadIdx.x;
    const int lane = tid & 31, wid = tid >> 5;
    const int wm = wid & 1, wn = wid >> 1;                  // warp tile 64(M) x 32(N)
    const int bm = blockIdx.y * BM, bn = blockIdx.x * BN;

    const int lrow = tid >> 2;                              // 0..63
    const int lpart = (tid & 3) * 8;                        // halfs
    const size_t rstep = (size_t)64 * H_DIM;
    const half* gAh = g_xhi  + (size_t)(bm + lrow) * H_DIM + lpart;
    const half* gAl = g_xlo  + (size_t)(bm + lrow) * H_DIM + lpart;
    const half* gBh = g_wihi + (size_t)(bn + lrow) * H_DIM + lpart;
    const half* gBl = g_wilo + (size_t)(bn + lrow) * H_DIM + lpart;

    half* pA0 = &sAh[lrow * SSTR + lpart]; half* pA1 = pA0 + 64 * SSTR;
    half* pL0 = &sAl[lrow * SSTR + lpart]; half* pL1 = pL0 + 64 * SSTR;
    half* pB0 = &sBh[lrow * SSTR + lpart]; half* pB1 = pB0 + 64 * SSTR;
    half* pC0 = &sBl[lrow * SSTR + lpart]; half* pC1 = pC0 + 64 * SSTR;

    float d[4][4][4];
#pragma unroll
    for (int i = 0; i < 4; i++)
#pragma unroll
        for (int j = 0; j < 4; j++)
#pragma unroll
            for (int v = 0; v < 4; v++) d[i][j][v] = 0.f;

    uint4 vah0 = *(const uint4*)(gAh);           uint4 vah1 = *(const uint4*)(gAh + rstep);
    uint4 val0 = *(const uint4*)(gAl);           uint4 val1 = *(const uint4*)(gAl + rstep);
    uint4 vbh0 = *(const uint4*)(gBh);           uint4 vbh1 = *(const uint4*)(gBh + rstep);
    uint4 vbl0 = *(const uint4*)(gBl);           uint4 vbl1 = *(const uint4*)(gBl + rstep);

    for (int k0 = 0; k0 < H_DIM; k0 += BK) {
        __syncthreads();
        *(uint4*)pA0 = vah0; *(uint4*)pA1 = vah1;
        *(uint4*)pL0 = val0; *(uint4*)pL1 = val1;
        *(uint4*)pB0 = vbh0; *(uint4*)pB1 = vbh1;
        *(uint4*)pC0 = vbl0; *(uint4*)pC1 = vbl1;
        __syncthreads();
        if (k0 + BK < H_DIM) {
            vah0 = *(const uint4*)(gAh + k0 + BK); vah1 = *(const uint4*)(gAh + k0 + BK + rstep);
            val0 = *(const uint4*)(gAl + k0 + BK); val1 = *(const uint4*)(gAl + k0 + BK + rstep);
            vbh0 = *(const uint4*)(gBh + k0 + BK); vbh1 = *(const uint4*)(gBh + k0 + BK + rstep);
            vbl0 = *(const uint4*)(gBl + k0 + BK); vbl1 = *(const uint4*)(gBl + k0 + BK + rstep);
        }
#pragma unroll
        for (int kk = 0; kk < 2; kk++) {
            const int kh = kk * 16;
            const int ar = lane >> 2, ak = 2 * (lane & 3);
            uint32_t afh[4][4], afl[4][4], bfh[4][2], bfl[4][2];
#pragma unroll
            for (int i = 0; i < 4; i++) {
                const int ro = (wm * 64 + i * 16 + ar) * SSTR + kh + ak;
                const half* ph = &sAh[ro];
                afh[i][0] = *(const uint32_t*)ph;
                afh[i][1] = *(const uint32_t*)(ph + 8 * SSTR);
                afh[i][2] = *(const uint32_t*)(ph + 8);
                afh[i][3] = *(const uint32_t*)(ph + 8 * SSTR + 8);
                const half* pl = &sAl[ro];
                afl[i][0] = *(const uint32_t*)pl;
                afl[i][1] = *(const uint32_t*)(pl + 8 * SSTR);
                afl[i][2] = *(const uint32_t*)(pl + 8);
                afl[i][3] = *(const uint32_t*)(pl + 8 * SSTR + 8);
            }
#pragma unroll
            for (int j = 0; j < 4; j++) {
                const int ro = (wn * 32 + j * 8 + ar) * SSTR + kh + ak;
                const half* ph = &sBh[ro];
                bfh[j][0] = *(const uint32_t*)ph;
                bfh[j][1] = *(const uint32_t*)(ph + 8);
                const half* pl = &sBl[ro];
                bfl[j][0] = *(const uint32_t*)pl;
                bfl[j][1] = *(const uint32_t*)(pl + 8);
            }
#pragma unroll
            for (int i = 0; i < 4; i++)
#pragma unroll
                for (int j = 0; j < 4; j++) {
                    mma16816(d[i][j], afh[i], bfh[j]);   // xhi @ whi
                    mma16816(d[i][j], afh[i], bfl[j]);   // xhi @ wlo
                    mma16816(d[i][j], afl[i], bfh[j]);   // xlo @ whi
                }
        }
    }

#pragma unroll
    for (int i = 0; i < 4; i++) {
        int r = bm + wm * 64 + i * 16 + (lane >> 2);
#pragma unroll
        for (int j = 0; j < 4; j++) {
            int c = bn + wn * 32 + j * 8 + 2 * (lane & 3);
            float b0 = bias[c], b1 = bias[c + 1];
            float* o0 = &g_xwi[(size_t)r * G4 + c];
            float* o1 = o0 + (size_t)8 * G4;
            o0[0] = d[i][j][0] + b0;
            o0[1] = d[i][j][1] + b1;
            o1[0] = d[i][j][2] + b0;
            o1[1] = d[i][j][3] + b1;
        }
    }
}

// ------------------------- persistent LSTM recurrence -----------------------
__device__ __forceinline__ float sigf(float x) { return 1.f / (1.f + __expf(-x)); }
__device__ __forceinline__ float tanhfast(float x) { return 1.f - 2.f / (__expf(2.f * x) + 1.f); }

// 16 warps: warp w -> column group (w>>1) of 7 cols, k-half (w&1) of 1024.
// Cols 0,1 of each warp's group are register-resident (cuts smem crossbar 29%).
// Gate tail parallelized over 56 threads + named barrier.
// out layout: [ c_f (H) | h_f (H) | ys (T*H) ]
__global__ void __launch_bounds__(RTH, 1) k_lstm(
    const float* __restrict__ c0, float* __restrict__ out)
{
    extern __shared__ __align__(16) half sW[];   // [COLS][H_DIM]
    __shared__ float ybuf[2 * COLS];
    __shared__ float abuf[COLS];                 // activations

    const int tid = threadIdx.x;
    const int wid = tid >> 5, lane = tid & 31;
    const int cg = wid >> 1;          // 0..7: column group (7 cols)
    const int kh = wid & 1;           // k half: 0 or 1
    const int d0 = blockIdx.x * DPC;
    float* ys = out + 2 * H_DIM;

    // load this CTA's 56 weight columns into smem (coalesced, once per run)
    const int NV = COLS * (H_DIM / 8);
    for (int i = tid; i < NV; i += RTH) {
        int c = i >> 8;                 // / (H_DIM/8)
        int k8 = (i & 255) * 8;
        int gate = c / DPC, di = c - gate * DPC;
        int dgc = d0 + di;
        uint4 v = make_uint4(0u, 0u, 0u, 0u);
        if (dgc < H_DIM)
            v = *(const uint4*)&g_whT[((size_t)(gate * H_DIM + dgc)) * H_DIM + k8];
        *(uint4*)&sW[(size_t)c * H_DIM + k8] = v;
    }
    __syncthreads();

    // register-resident weights for cols 0,1 of this warp's group (32 regs)
    uint4 wreg[2][4];
#pragma unroll
    for (int j = 0; j < 2; j++)
#pragma unroll
        for (int m = 0; m < 4; m++) {
            const int kb = kh * 1024 + (m * 32 + lane) * 8;
            wreg[j][m] = *(const uint4*)&sW[(size_t)(cg * 7 + j) * H_DIM + kb];
        }

    // gate-col thread mapping: tid < 56 -> col tid (gate = tid/14, unit = tid%14)
    const bool gc = (tid < COLS);
    const int  gcol_gate = tid / DPC;         // valid when gc
    const int  gcol_unit = tid - gcol_gate * DPC;
    const int  dg_gc = d0 + gcol_unit;        // unit index of this col
    const bool gc_ok = gc && (dg_gc < H_DIM);

    // combine threads: tid < 14
    const int dg = d0 + tid;
    const bool gt = (tid < DPC) && (dg < H_DIM);

    float c_state = gt ? c0[dg] : 0.f;
    float h_last = 0.f;

    // per-col xw prefetch for step 0
    float xw_own = 0.f;
    if (gc_ok)
        xw_own = g_xwi[(size_t)gcol_gate * H_DIM + dg_gc];
    __syncthreads();

    for (int t = 0; t < T_LEN; t++) {
        // fp16 h of previous step (double-buffered; L2-coherent loads), this k-half
        const uint4* hsrc = (const uint4*)&g_hh[(t & 1) ^ 1][kh * 1024];
        uint4 hv[4];
#pragma unroll
        for (int m = 0; m < 4; m++) hv[m] = __ldcg(hsrc + m * 32 + lane);

        float acc[7];
#pragma unroll
        for (int j = 0; j < 7; j++) acc[j] = 0.f;

#pragma unroll
        for (int m = 0; m < 4; m++) {
            const int kb = kh * 1024 + (m * 32 + lane) * 8;
            const half2 h0 = *reinterpret_cast<const half2*>(&hv[m].x);
            const half2 h1 = *reinterpret_cast<const half2*>(&hv[m].y);
            const half2 h2 = *reinterpret_cast<const half2*>(&hv[m].z);
            const half2 h3 = *reinterpret_cast<const half2*>(&hv[m].w);
            // cols 0,1 from registers (no smem traffic)
#pragma unroll
            for (int j = 0; j < 2; j++) {
                uint4 wv = wreg[j][m];
                half2 p = __hmul2(*reinterpret_cast<half2*>(&wv.x), h0);
                p = __hfma2(*reinterpret_cast<half2*>(&wv.y), h1, p);
                p = __hfma2(*reinterpret_cast<half2*>(&wv.z), h2, p);
                p = __hfma2(*reinterpret_cast<half2*>(&wv.w), h3, p);
                float2 pf = __half22float2(p);
                acc[j] += pf.x + pf.y;
            }
            // cols 2..6 from smem
#pragma unroll
            for (int j = 2; j < 7; j++) {
                uint4 wv = *(const uint4*)&sW[(size_t)(cg * 7 + j) * H_DIM + kb];
                half2 p = __hmul2(*reinterpret_cast<half2*>(&wv.x), h0);
                p = __hfma2(*reinterpret_cast<half2*>(&wv.y), h1, p);
                p = __hfma2(*reinterpret_cast<half2*>(&wv.z), h2, p);
                p = __hfma2(*reinterpret_cast<half2*>(&wv.w), h3, p);
                float2 pf = __half22float2(p);
                acc[j] += pf.x + pf.y;
            }
        }

#pragma unroll
        for (int j = 0; j < 7; j++) {
            float v = acc[j];
            v += __shfl_xor_sync(0xffffffffu, v, 16);
            v += __shfl_xor_sync(0xffffffffu, v, 8);
            v += __shfl_xor_sync(0xffffffffu, v, 4);
            v += __shfl_xor_sync(0xffffffffu, v, 2);
            v += __shfl_xor_sync(0xffffffffu, v, 1);
            if (lane == 0) ybuf[kh * COLS + cg * 7 + j] = v;
        }
        __syncthreads();                                   // (A) ybuf ready

        // ---- parallel gate tail: warps 0,1 ----
        if (wid < 2) {
            if (gc) {
                float y = ybuf[tid] + ybuf[COLS + tid] + xw_own;
                // gates 0(i),1(f),3(o): sigmoid; gate 2(g): tanh
                abuf[tid] = (gcol_gate == 2) ? tanhfast(y) : sigf(y);
            }
            asm volatile("bar.sync 1, 64;" ::: "memory");  // warps 0,1 only
            if (gt) {
                float ig = abuf[tid];
                float fg = abuf[DPC + tid];
                float gg = abuf[2 * DPC + tid];
                float og = abuf[3 * DPC + tid];
                c_state = fg * c_state + ig * gg;
                h_last = og * tanhfast(c_state);
                g_hh[t & 1][dg] = __float2half_rn(h_last); // broadcast first
                // arrival directly after broadcast store (same warp ordering)
                __threadfence();                           // release
                if (tid == 0) atomicAdd(&g_cnt[0], 1u);    // REDG, no return
                ys[(size_t)t * H_DIM + dg] = h_last;       // off critical path
            }
            // prefetch next xw during the global wait (hides DRAM latency)
            if (gc_ok && t + 1 < T_LEN)
                xw_own = g_xwi[(size_t)(t + 1) * G4 + (size_t)gcol_gate * H_DIM + dg_gc];
        }
        // single poller, single volatile word, tight spin (R13/R16-proven)
        if (tid == RTH - 1) {
            volatile unsigned* pc = &g_cnt[0];
            const unsigned tgt = (unsigned)(t + 1) * (unsigned)NCTA;
            while (*pc < tgt) { }
            __threadfence();                               // acquire
        }
        __syncthreads();                                   // (B) release all
    }

    if (gt) {
        out[dg] = c_state;           // c_f
        out[H_DIM + dg] = h_last;    // h_f
    }
}

// ------------------------- launch -------------------------------------------
extern "C" void kernel_launch(void* const* d_in, const int* in_sizes, int n_in,
                              void* d_out, int out_size) {
    const float* x  = (const float*)d_in[0];
    const float* c0 = (const float*)d_in[1];
    const float* h0 = (const float*)d_in[2];
    const float* Wi = (const float*)d_in[3];
    const float* Wh = (const float*)d_in[4];
    const float* b  = (const float*)d_in[5];
    float* out = (float*)d_out;

    (void)in_sizes; (void)n_in; (void)out_size;

    static int attr_set = 0;
    const int gemm_smem = 4 * BM * SSTR * (int)sizeof(half);        // 57344
    const int lstm_smem = COLS * H_DIM * (int)sizeof(half);         // 229376
    if (!attr_set) {
        cudaFuncSetAttribute(k_gemm, cudaFuncAttributeMaxDynamicSharedMemorySize, gemm_smem);
        cudaFuncSetAttribute(k_lstm, cudaFuncAttributeMaxDynamicSharedMemorySize, lstm_smem);
        attr_set = 1;
    }

    // launch order keeps k_lstm as the 4th launch -> ncu (-s5 -c1) profiles it
    k_split_x<<<(T_LEN * H_DIM + 255) / 256, 256>>>(x);
    k_tr_all<<<dim3(G4 / 32, H_DIM / 32, 2), dim3(32, 8)>>>(Wi, Wh, h0);

    dim3 gg(G4 / BN, T_LEN / BM);
    k_gemm<<<gg, 256, gemm_smem>>>(b);

    k_lstm<<<NCTA, RTH, lstm_smem>>>(c0, out);
}